// round 2
// baseline (speedup 1.0000x reference)
#include <cuda_runtime.h>

// Sliding-window minimum, window = [t, t+256] (257 elems), 'last' padding.
// out[b,t] = min_{i=t..t+256} sig[b, min(i, T-1)]
//
// Chunk-16 prefix/suffix decomposition: window len 257 = (16-m) + 15*16 + (m+1)
// for any phase m = t%16 -> out = min( suf16[t], 15 full-chunk mins, pre16[t+256] ).
//
// 512 threads cover the 512 input positions a 256-output block needs (one
// shuffle-scan rep per thread); threads 0..255 then assemble outputs with a
// depth-4 fmin tree over broadcast chunk mins.

#define OUTB 256   // outputs per block
#define THR  512   // threads per block (= OUTB + window span)

__global__ __launch_bounds__(THR) void always_window_min(
    const float* __restrict__ sig, float* __restrict__ out, int T)
{
    const int b    = blockIdx.y;
    const int t0   = blockIdx.x * OUTB;
    const int p    = threadIdx.x;            // local position in [0, 512)
    const int lane = p & 31;

    __shared__ float sSuf[OUTB];             // suffix-min within 16-chunk, pos [0,256)
    __shared__ float sPreHi[OUTB];           // prefix-min within 16-chunk, pos [256,512)
    __shared__ float sChunk[THR / 16];       // full-chunk mins, 32 chunks

    const float* row = sig + (size_t)b * T;

    int g = t0 + p;
    g = g < T - 1 ? g : T - 1;               // 'last' padding clamp
    float x = __ldg(row + g);

    // 16-segmented inclusive prefix/suffix min scans (lane%16 == p%16).
    float pre = x, suf = x;
    #pragma unroll
    for (int d = 1; d < 16; d <<= 1) {
        float up = __shfl_up_sync(0xffffffffu, pre, d);
        if ((lane & 15) >= d) pre = fminf(pre, up);
        float dn = __shfl_down_sync(0xffffffffu, suf, d);
        if ((lane & 15) < 16 - d) suf = fminf(suf, dn);
    }

    if (p < OUTB)        sSuf[p] = suf;
    else                 sPreHi[p - OUTB] = pre;
    if ((p & 15) == 15)  sChunk[p >> 4] = pre;   // chunk min = prefix at chunk end
    __syncthreads();

    if (p < OUTB) {
        const int c = p >> 4;                // own chunk
        // 15 full chunks c+1 .. c+15 (max index 30 < 32). Broadcast LDS reads.
        float v0  = sChunk[c + 1],  v1  = sChunk[c + 2],  v2  = sChunk[c + 3];
        float v3  = sChunk[c + 4],  v4  = sChunk[c + 5],  v5  = sChunk[c + 6];
        float v6  = sChunk[c + 7],  v7  = sChunk[c + 8],  v8  = sChunk[c + 9];
        float v9  = sChunk[c + 10], v10 = sChunk[c + 11], v11 = sChunk[c + 12];
        float v12 = sChunk[c + 13], v13 = sChunk[c + 14], v14 = sChunk[c + 15];
        // depth-4 tree + head/tail pieces
        float a0 = fminf(v0,  v1),  a1 = fminf(v2,  v3);
        float a2 = fminf(v4,  v5),  a3 = fminf(v6,  v7);
        float a4 = fminf(v8,  v9),  a5 = fminf(v10, v11);
        float a6 = fminf(v12, v13), a7 = fminf(v14, sPreHi[p]); // pre at p+256
        float b0 = fminf(a0, a1), b1 = fminf(a2, a3);
        float b2 = fminf(a4, a5), b3 = fminf(a6, a7);
        float c0 = fminf(b0, b1), c1 = fminf(b2, b3);
        float m  = fminf(fminf(c0, c1), sSuf[p]);

        out[(size_t)b * T + t0 + p] = m;
    }
}

extern "C" void kernel_launch(void* const* d_in, const int* in_sizes, int n_in,
                              void* d_out, int out_size)
{
    const float* sig = (const float*)d_in[0];
    float* out = (float*)d_out;

    const int T = 8192;                      // per reference setup_inputs
    const int B = in_sizes[0] / T;           // = 4

    dim3 grid(T / OUTB, B);
    always_window_min<<<grid, THR>>>(sig, out, T);
}